// round 12
// baseline (speedup 1.0000x reference)
#include <cuda_runtime.h>
#include <cstdint>
#include <cstddef>

#define NX  256
#define NU  32
#define NY  32
#define BB  16
#define TT  8192
#define LCH 64            // chunk length
#define NCH 128           // TT / LCH
#define ZS  68            // ZT row stride (LCH + 4 pad)
#define KTOT (NX + NU)    // 288
#define KHALF 144
// pass3 smem (floats): ZT[288][68] + R = max(BzT 8192, W 9216)
#define SM_R      (KTOT * ZS)            // 19584
#define SM_FLOATS (SM_R + 9216)          // 28800 -> 115200 B

// pass1 smem layout (floats)
#define P1_BZ 0                          // [32][256]
#define P1_UT (32 * NX)                  // [32][68]
#define P1_V  (P1_UT + 32 * 68)          // [256][68]
#define P1_FLOATS (P1_V + NX * 68)       // 27776 -> 111104 B

typedef unsigned long long ull;

// -------- device scratch (allocation-free; ~0.6 MB total) --------
__device__ float g_BzT[NU * NX];          // [u][n]
__device__ float g_CzT[NX * NY];          // [n][y]
__device__ float g_DT [NU * NY];          // [u][y]
__device__ float g_z0 [BB * NX];
__device__ float g_w  [BB * NCH * NX];
__device__ float g_ss [BB * NCH * NX];

// -------- f32x2 helpers --------
__device__ __forceinline__ void ffma2(ull& d, ull a, ull b) {
    asm("fma.rn.f32x2 %0, %1, %2, %0;" : "+l"(d) : "l"(a), "l"(b));
}
__device__ __forceinline__ ull addf2(ull a, ull b) {
    ull r; asm("add.rn.f32x2 %0, %1, %2;" : "=l"(r) : "l"(a), "l"(b)); return r;
}
__device__ __forceinline__ ull dup2(float x) {
    ull r; asm("mov.b64 %0, {%1, %1};" : "=l"(r) : "f"(x)); return r;
}
__device__ __forceinline__ float2 unpk(ull a) {
    float2 f; asm("mov.b64 {%0, %1}, %2;" : "=f"(f.x), "=f"(f.y) : "l"(a)); return f;
}
union F4U2 { float4 f; ull u[2]; };

// -------- prep: Bz, Cz, z0, D^T (4-way ILP) --------
__global__ __launch_bounds__(256) void prep_kernel(
    const float* __restrict__ x0, const float* __restrict__ Q,
    const float* __restrict__ Bmat, const float* __restrict__ C,
    const float* __restrict__ D)
{
    int idx = blockIdx.x * 256 + threadIdx.x;
    if (idx < NU * NX) {
        int u = idx >> 8, n = idx & 255;
        float a0 = 0.f, a1 = 0.f, a2 = 0.f, a3 = 0.f;
        #pragma unroll 4
        for (int i = 0; i < NX; i += 4) {
            a0 = fmaf(Q[(i + 0) * NX + n], Bmat[(i + 0) * NU + u], a0);
            a1 = fmaf(Q[(i + 1) * NX + n], Bmat[(i + 1) * NU + u], a1);
            a2 = fmaf(Q[(i + 2) * NX + n], Bmat[(i + 2) * NU + u], a2);
            a3 = fmaf(Q[(i + 3) * NX + n], Bmat[(i + 3) * NU + u], a3);
        }
        g_BzT[u * NX + n] = (a0 + a1) + (a2 + a3);
    } else if (idx < NU * NX + NY * NX) {
        int j = idx - NU * NX;
        int y = j >> 8, n = j & 255;
        float a0 = 0.f, a1 = 0.f, a2 = 0.f, a3 = 0.f;
        #pragma unroll 4
        for (int i = 0; i < NX; i += 4) {
            a0 = fmaf(C[y * NX + i + 0], Q[(i + 0) * NX + n], a0);
            a1 = fmaf(C[y * NX + i + 1], Q[(i + 1) * NX + n], a1);
            a2 = fmaf(C[y * NX + i + 2], Q[(i + 2) * NX + n], a2);
            a3 = fmaf(C[y * NX + i + 3], Q[(i + 3) * NX + n], a3);
        }
        g_CzT[n * NY + y] = (a0 + a1) + (a2 + a3);
    } else if (idx < NU * NX + NY * NX + BB * NX) {
        int j = idx - NU * NX - NY * NX;
        int b = j >> 8, n = j & 255;
        float a0 = 0.f, a1 = 0.f, a2 = 0.f, a3 = 0.f;
        #pragma unroll 4
        for (int i = 0; i < NX; i += 4) {
            a0 = fmaf(x0[b * NX + i + 0], Q[(i + 0) * NX + n], a0);
            a1 = fmaf(x0[b * NX + i + 1], Q[(i + 1) * NX + n], a1);
            a2 = fmaf(x0[b * NX + i + 2], Q[(i + 2) * NX + n], a2);
            a3 = fmaf(x0[b * NX + i + 3], Q[(i + 3) * NX + n], a3);
        }
        g_z0[b * NX + n] = (a0 + a1) + (a2 + a3);
    } else if (idx < NU * NX + NY * NX + BB * NX + NU * NY) {
        int j = idx - NU * NX - NY * NX - BB * NX;
        int u = j >> 5, y = j & 31;
        g_DT[u * NY + y] = D[y * NU + u];
    }
}

// -------- pass1: V GEMM -> smem, Horner only (NO v store) --------
__global__ __launch_bounds__(256, 2) void pass1_kernel(
    const float* __restrict__ u, const float* __restrict__ lam)
{
    extern __shared__ float sm[];
    float* s_bz = sm + P1_BZ;     // [32 u][256 n]
    float* s_ut = sm + P1_UT;     // [32 u][68]
    float* s_v  = sm + P1_V;      // [256 n][68]

    int b   = blockIdx.x >> 7;
    int c   = blockIdx.x & (NCH - 1);
    int tid = threadIdx.x;
    const size_t chunk = (size_t)b * TT + (size_t)c * LCH;
    const float* ub = u + chunk * NU;

    #pragma unroll
    for (int i = 0; i < 8; i++)
        ((float4*)s_bz)[tid + i * 256] = ((const float4*)g_BzT)[tid + i * 256];
    #pragma unroll
    for (int i = 0; i < 8; i++) {
        int e = tid + i * 256;
        int t = e >> 5, uu = e & 31;
        s_ut[uu * 68 + t] = ub[e];
    }
    __syncthreads();

    int a  = tid >> 3;
    int bq = tid & 7;
    ull acc[8][4];
    #pragma unroll
    for (int i = 0; i < 8; i++)
        #pragma unroll
        for (int j = 0; j < 4; j++) acc[i][j] = 0;

    #pragma unroll 8
    for (int k = 0; k < 32; k++) {
        float4 n0 = *(const float4*)(s_bz + k * NX + 8 * a);
        float4 n1 = *(const float4*)(s_bz + k * NX + 8 * a + 4);
        F4U2 t0; t0.f = *(const float4*)(s_ut + k * 68 + 8 * bq);
        F4U2 t1; t1.f = *(const float4*)(s_ut + k * 68 + 8 * bq + 4);
        float nv[8] = {n0.x, n0.y, n0.z, n0.w, n1.x, n1.y, n1.z, n1.w};
        #pragma unroll
        for (int i = 0; i < 8; i++) {
            ull nd = dup2(nv[i]);
            ffma2(acc[i][0], nd, t0.u[0]);
            ffma2(acc[i][1], nd, t0.u[1]);
            ffma2(acc[i][2], nd, t1.u[0]);
            ffma2(acc[i][3], nd, t1.u[1]);
        }
    }
    #pragma unroll
    for (int i = 0; i < 8; i++) {
        float2 p0 = unpk(acc[i][0]), p1 = unpk(acc[i][1]);
        float2 p2 = unpk(acc[i][2]), p3 = unpk(acc[i][3]);
        float* row = s_v + (8 * a + i) * 68 + 8 * bq;
        *(float4*)(row)     = make_float4(p0.x, p0.y, p1.x, p1.y);
        *(float4*)(row + 4) = make_float4(p2.x, p2.y, p3.x, p3.y);
    }
    __syncthreads();

    {
        float lamn = lam[tid];
        float w = 0.f;
        const float* vr = s_v + tid * 68;
        #pragma unroll
        for (int q = 0; q < 16; q++) {         // stride-17 f4: conflict-free
            float4 vq = *(const float4*)(vr + 4 * q);
            w = fmaf(lamn, w, vq.x);
            w = fmaf(lamn, w, vq.y);
            w = fmaf(lamn, w, vq.z);
            w = fmaf(lamn, w, vq.w);
        }
        g_w[((size_t)b * NCH + c) * NX + tid] = w;
    }
}

// -------- chunkscan --------
__global__ __launch_bounds__(256) void chunkscan_kernel(const float* __restrict__ lam)
{
    int b = blockIdx.x;
    int n = threadIdx.x;
    float lamL = lam[n];
    #pragma unroll
    for (int i = 0; i < 6; i++) lamL *= lamL;   // lam^64
    float s = g_z0[b * NX + n];
    const size_t base = (size_t)b * NCH * NX + n;
    for (int cg = 0; cg < NCH / 16; cg++) {
        float wv[16];
        #pragma unroll
        for (int i = 0; i < 16; i++)
            wv[i] = g_w[base + (size_t)(cg * 16 + i) * NX];
        #pragma unroll
        for (int i = 0; i < 16; i++) {
            g_ss[base + (size_t)(cg * 16 + i) * NX] = s;
            s = fmaf(lamL, s, wv[i]);
        }
    }
}

// -------- pass3: v-GEMM (recompute) + in-smem scan + y-GEMM --------
__global__ __launch_bounds__(256, 2) void pass3_kernel(
    const float* __restrict__ u, const float* __restrict__ lam,
    float* __restrict__ y)
{
    extern __shared__ float sm[];
    float* ZT = sm;               // [288][68]: rows 0-255 v->z, 256-287 u^T
    float* R  = sm + SM_R;        // overlay: BzT [32][256], then W [288][32]

    int b    = blockIdx.x >> 7;
    int c    = blockIdx.x & (NCH - 1);
    int tid  = threadIdx.x;
    int w    = tid >> 5;
    int lane = tid & 31;
    const size_t chunk = (size_t)b * TT + (size_t)c * LCH;
    const float* ub = u + chunk * NU;

    // ---- phase 1: u^T -> ZT rows 256.., BzT -> R ----
    #pragma unroll
    for (int i = 0; i < 8; i++) {
        int e = tid + i * 256;
        int t = e >> 5, uu = e & 31;
        ZT[(NX + uu) * ZS + t] = ub[e];
    }
    #pragma unroll
    for (int i = 0; i < 8; i++)
        ((float4*)R)[tid + i * 256] = ((const float4*)g_BzT)[tid + i * 256];
    __syncthreads();

    // ---- phase 2: v-GEMM (8n x 8t per thread, K=32) -> ZT rows 0-255 ----
    {
        int a  = tid >> 3;
        int bq = tid & 7;
        ull acc[8][4];
        #pragma unroll
        for (int i = 0; i < 8; i++)
            #pragma unroll
            for (int j = 0; j < 4; j++) acc[i][j] = 0;

        #pragma unroll 8
        for (int k = 0; k < 32; k++) {
            float4 n0 = *(const float4*)(R + k * NX + 8 * a);
            float4 n1 = *(const float4*)(R + k * NX + 8 * a + 4);
            F4U2 t0; t0.f = *(const float4*)(ZT + (NX + k) * ZS + 8 * bq);
            F4U2 t1; t1.f = *(const float4*)(ZT + (NX + k) * ZS + 8 * bq + 4);
            float nv[8] = {n0.x, n0.y, n0.z, n0.w, n1.x, n1.y, n1.z, n1.w};
            #pragma unroll
            for (int i = 0; i < 8; i++) {
                ull nd = dup2(nv[i]);
                ffma2(acc[i][0], nd, t0.u[0]);
                ffma2(acc[i][1], nd, t0.u[1]);
                ffma2(acc[i][2], nd, t1.u[0]);
                ffma2(acc[i][3], nd, t1.u[1]);
            }
        }
        #pragma unroll
        for (int i = 0; i < 8; i++) {
            float2 p0 = unpk(acc[i][0]), p1 = unpk(acc[i][1]);
            float2 p2 = unpk(acc[i][2]), p3 = unpk(acc[i][3]);
            float* row = ZT + (8 * a + i) * ZS + 8 * bq;
            *(float4*)(row)     = make_float4(p0.x, p0.y, p1.x, p1.y);
            *(float4*)(row + 4) = make_float4(p2.x, p2.y, p3.x, p3.y);
        }
    }
    __syncthreads();

    // ---- phase 3: W = [Cz; D^T] -> R (ALL 9216 floats); scan ZT row tid ----
    #pragma unroll
    for (int i = 0; i < 36; i++) {
        int e = tid + i * 256;
        R[e] = (e < NX * NY) ? g_CzT[e] : g_DT[e - NX * NY];
    }
    {
        float lamn = lam[tid];
        float S = g_ss[((size_t)b * NCH + c) * NX + tid];
        float* zr = ZT + tid * ZS;
        #pragma unroll
        for (int q = 0; q < 16; q++) {         // stride-17 f4: conflict-free
            float4 vq = *(const float4*)(zr + 4 * q);
            float4 zq;
            zq.x = S; S = fmaf(lamn, S, vq.x);
            zq.y = S; S = fmaf(lamn, S, vq.y);
            zq.z = S; S = fmaf(lamn, S, vq.z);
            zq.w = S; S = fmaf(lamn, S, vq.w);
            *(float4*)(zr + 4 * q) = zq;       // z_prev in place
        }
    }
    __syncthreads();

    // ---- phase 4: y-GEMM (K-split 2, validated R9) ----
    int half = w >> 2;
    int wq   = w & 3;
    int th   = lane >> 4;
    int yp   = lane & 15;
    int tb   = 16 * wq + 8 * th;

    ull acc[8];
    #pragma unroll
    for (int i = 0; i < 8; i++) acc[i] = 0;

    const float* zk = ZT + half * KHALF * ZS + tb;
    const float* wk = R + half * KHALF * NY + 2 * yp;
    #pragma unroll 4
    for (int k = 0; k < KHALF; k++) {
        F4U2 zA; zA.f = *(const float4*)(zk);
        F4U2 zB; zB.f = *(const float4*)(zk + 4);
        float2 wv = *(const float2*)(wk);
        ull w0 = dup2(wv.x), w1 = dup2(wv.y);
        ffma2(acc[0], zA.u[0], w0); ffma2(acc[1], zA.u[0], w1);
        ffma2(acc[2], zA.u[1], w0); ffma2(acc[3], zA.u[1], w1);
        ffma2(acc[4], zB.u[0], w0); ffma2(acc[5], zB.u[0], w1);
        ffma2(acc[6], zB.u[1], w0); ffma2(acc[7], zB.u[1], w1);
        zk += ZS; wk += NY;
    }

    __syncthreads();
    ull* red = (ull*)ZT;
    int slot = (wq * 32 + lane) * 17;
    if (half == 1) {
        #pragma unroll
        for (int i = 0; i < 8; i++) red[slot + i] = acc[i];
    }
    __syncthreads();
    if (half == 0) {
        float* yrow = y + chunk * NY;
        #pragma unroll
        for (int tp = 0; tp < 4; tp++) {
            ull a0 = addf2(acc[2 * tp + 0], red[slot + 2 * tp + 0]);
            ull a1 = addf2(acc[2 * tp + 1], red[slot + 2 * tp + 1]);
            float2 f0 = unpk(a0);
            float2 f1 = unpk(a1);
            int t0 = tb + 2 * tp;
            *(float2*)(yrow + (size_t)t0 * NY + 2 * yp) =
                make_float2(f0.x, f1.x);
            *(float2*)(yrow + (size_t)(t0 + 1) * NY + 2 * yp) =
                make_float2(f0.y, f1.y);
        }
    }
}

// -------- launch --------
extern "C" void kernel_launch(void* const* d_in, const int* in_sizes, int n_in,
                              void* d_out, int out_size)
{
    const float* x0   = (const float*)d_in[0];
    const float* u    = (const float*)d_in[1];
    const float* Q    = (const float*)d_in[2];
    const float* lam  = (const float*)d_in[3];
    const float* Bmat = (const float*)d_in[4];
    const float* C    = (const float*)d_in[5];
    const float* D    = (const float*)d_in[6];
    float* y = (float*)d_out;
    (void)in_sizes; (void)n_in; (void)out_size;

    static int attr_set = 0;
    if (!attr_set) {
        cudaFuncSetAttribute(pass3_kernel,
                             cudaFuncAttributeMaxDynamicSharedMemorySize,
                             SM_FLOATS * (int)sizeof(float));
        cudaFuncSetAttribute(pass1_kernel,
                             cudaFuncAttributeMaxDynamicSharedMemorySize,
                             P1_FLOATS * (int)sizeof(float));
        attr_set = 1;
    }

    prep_kernel<<<84, 256>>>(x0, Q, Bmat, C, D);
    pass1_kernel<<<BB * NCH, 256, P1_FLOATS * sizeof(float)>>>(u, lam);
    chunkscan_kernel<<<BB, 256>>>(lam);
    pass3_kernel<<<BB * NCH, 256, SM_FLOATS * sizeof(float)>>>(u, lam, y);
}